// round 14
// baseline (speedup 1.0000x reference)
#include <cuda_runtime.h>
#include <cuda_bf16.h>

// WTA / row-wise top-k(=64) scatter-to-dense, exact incl. stable tie-breaking.
// PERSISTENT grid-stride CTAs (grid = resident capacity), row as raw floats
// in registers (4x float4, TPB=512). No SMEM staging: phase skew between
// co-resident CTAs accumulates across iterations and smooths DRAM demand.
// Per-row fast path (valid when count(f>=2.0) >= k; 9-sigma for N(0,1)):
//   (1) fused 128-bin histogram of (bits>>17)-0x2000 over f >= 2.0 with
//       per-bin slot capture of full bits ([2,6) spans bins 0..95;
//       >=6 clamps to bin 127, resolved exactly by the rank step)
//   (2) warp0: pick bin where reverse-cumulative crosses k (4-chunk suffix
//       scan), then rank the E (expected ~3, dynamically bounded) captured
//       elements with a shuffle loop -> exact k-th value + tie metadata
//   (3) output: out = (f >= thr) ? f : 0 ; rare stable tie-break by column.
// Generic fallback (cold, exact): 4-pass 256-bin radix select over fmap keys.

#define COLS  8192
#define TPB   512
#define VPT   4                    // float4 per thread -> 16 scalars
#define NW    (TPB / 32)
#define NBIN  128
#define SLOTS 16
#define FULL  0xffffffffu

__device__ __forceinline__ unsigned fmap_u(unsigned b) {
    return b ^ ((unsigned)((int)b >> 31) | 0x80000000u);
}
__device__ __forceinline__ float funmap(unsigned v) {
    unsigned mask = ((unsigned)((int)(~v) >> 31)) | 0x80000000u;
    return __uint_as_float(v ^ mask);
}

__global__ __launch_bounds__(TPB, 4)
void wta_topk_kernel(const float4* __restrict__ x4,
                     const int*    __restrict__ kp,
                     float4*       __restrict__ o4,
                     int rows)
{
    __shared__ unsigned sHist[256];          // fast path uses [0,128)
    __shared__ unsigned sBin[NBIN * SLOTS];
    __shared__ unsigned sWsum[NW];
    __shared__ unsigned sSel, sNeed, sEq, sThr, sFlag;

    const int tid  = threadIdx.x;
    const int lane = tid & 31;
    const int warp = tid >> 5;
    const unsigned k = (unsigned)__ldg(kp);
    const unsigned stride = gridDim.x;

    for (unsigned r = blockIdx.x; r < (unsigned)rows; r += stride) {
        const size_t base = (size_t)r * (COLS / 4) + tid;

        // ---- load row (raw floats) ----
        float4 v[VPT];
#pragma unroll
        for (int j = 0; j < VPT; j++)
            v[j] = __ldcs(&x4[base + (size_t)j * TPB]);

        if (tid < NBIN) sHist[tid] = 0u;
        if (tid == 0) sFlag = 0u;
        __syncthreads();                                          // S1

        // ---- (1) fused 128-bin histogram + slot capture over f >= 2.0 ----
#pragma unroll
        for (int j = 0; j < VPT; j++) {
#pragma unroll
            for (int c = 0; c < 4; c++) {
                const float f = (c == 0) ? v[j].x : (c == 1) ? v[j].y
                              : (c == 2) ? v[j].z : v[j].w;
                if (f >= 2.0f) {
                    const unsigned bits = __float_as_uint(f);
                    unsigned b = (bits >> 17) - 0x2000u;   // 2.0 -> bin 0
                    b = min(b, 127u);
                    const unsigned p = atomicAdd(&sHist[b], 1u);
                    if (p < SLOTS) sBin[(b << 4) + p] = bits;
                }
            }
        }
        __syncthreads();                                          // S2

        // ---- (2) warp0: bin select (4 chunks) + dynamic shuffle rank ----
        if (warp == 0) {
            unsigned hv4[4], tot[4];
#pragma unroll
            for (int c = 0; c < 4; c++) {
                hv4[c] = sHist[c * 32 + lane];
                tot[c] = __reduce_add_sync(FULL, hv4[c]);
            }
            unsigned suf = 0u, tch = 0u, exC = 0u;
#pragma unroll
            for (int c = 3; c >= 0; c--) {
                if (suf < k && k <= suf + tot[c]) { tch = (unsigned)c; exC = suf; }
                suf += tot[c];
            }
            if (suf < k) {
                if (lane == 0) sFlag = 1u;
            } else {
                const unsigned hv = hv4[tch];
                unsigned incl = hv;        // suffix sum over higher bins
#pragma unroll
                for (int o = 1; o < 32; o <<= 1) {
                    const unsigned n = __shfl_down_sync(FULL, incl, o);
                    if (lane + o < 32) incl += n;
                }
                const unsigned excl = incl - hv;
                const bool fired = (exC + excl < k) && (k <= exC + incl);
                const unsigned fm = __ballot_sync(FULL, fired);
                const int src = __ffs(fm) - 1;
                const unsigned selBin = tch * 32u + (unsigned)src;
                const unsigned need1  = k - exC - __shfl_sync(FULL, excl, src);
                const unsigned E      = __shfl_sync(FULL, hv, src);
                if (E > SLOTS) {
                    if (lane == 0) sFlag = 1u;
                } else {
                    // exact rank among E captured keys (loop bounded by E,
                    // warp-uniform, expected ~3); positive-float bits compare
                    // identically to values.
                    const unsigned key = (lane < (int)E)
                                       ? sBin[(selBin << 4) + lane] : 0u;
                    unsigned gt = 0u, eq = 0u;
                    for (int o = 0; o < (int)E; o++) {
                        const unsigned other = __shfl_sync(FULL, key, o);
                        gt += (other > key) ? 1u : 0u;
                        eq += (other == key) ? 1u : 0u;
                    }
                    if (lane < (int)E && gt < need1 && need1 <= gt + eq) {
                        sThr  = key;        // unique key value fires
                        sNeed = need1 - gt;
                        sEq   = eq;
                    }
                }
            }
        }
        __syncthreads();                                          // S3

        float thrF;
        unsigned need, eqCnt;
        if (sFlag == 0u) {
            thrF  = __uint_as_float(sThr);
            need  = sNeed;
            eqCnt = sEq;
        } else {
            // ---- generic fallback: 4-pass 256-bin radix over fmap keys ----
            unsigned prefix = 0u;
            need = k;
#pragma unroll 1
            for (int p = 3; p >= 0; p--) {
                const int sh = 8 * p;
                __syncthreads();
                if (tid < 256) sHist[tid] = 0u;
                __syncthreads();
#pragma unroll 1
                for (int j = 0; j < VPT; j++) {
                    const float e[4] = { v[j].x, v[j].y, v[j].z, v[j].w };
#pragma unroll
                    for (int c = 0; c < 4; c++) {
                        const unsigned key = fmap_u(__float_as_uint(e[c]));
                        const bool m = (p == 3) ||
                                       (((key ^ prefix) >> (sh + 8)) == 0u);
                        if (m) atomicAdd(&sHist[(key >> sh) & 255u], 1u);
                    }
                }
                __syncthreads();
                if (warp == 0) {
                    unsigned hv8[8], tot[8];
#pragma unroll
                    for (int c = 0; c < 8; c++) {
                        hv8[c] = sHist[c * 32 + lane];
                        tot[c] = __reduce_add_sync(FULL, hv8[c]);
                    }
                    unsigned suf = 0u, tch = 0u, exC = 0u;
#pragma unroll
                    for (int c = 7; c >= 0; c--) {
                        if (suf < need && need <= suf + tot[c]) { tch = (unsigned)c; exC = suf; }
                        suf += tot[c];
                    }
                    const unsigned hv = hv8[tch];
                    unsigned incl = hv;
#pragma unroll
                    for (int o = 1; o < 32; o <<= 1) {
                        const unsigned n = __shfl_down_sync(FULL, incl, o);
                        if (lane + o < 32) incl += n;
                    }
                    const unsigned excl = incl - hv;
                    if (exC + excl < need && need <= exC + incl) {
                        sSel  = tch * 32 + (unsigned)lane;
                        sNeed = need - exC - excl;
                        sEq   = hv;
                    }
                }
                __syncthreads();
                prefix |= sSel << sh;
                need   = sNeed;
            }
            eqCnt = sEq;
            thrF  = funmap(prefix);
        }

        // ---- (3) output ----
        if (need == eqCnt) {
            // common path: keep all f >= thrF
#pragma unroll
            for (int j = 0; j < VPT; j++) {
                float4 o;
                o.x = (v[j].x >= thrF) ? v[j].x : 0.0f;
                o.y = (v[j].y >= thrF) ? v[j].y : 0.0f;
                o.z = (v[j].z >= thrF) ? v[j].z : 0.0f;
                o.w = (v[j].w >= thrF) ? v[j].w : 0.0f;
                __stcs(&o4[base + (size_t)j * TPB], o);
            }
        } else {
            // rare: stable tie-break, keep first `need` of ==thrF by column
            unsigned keepMask = 0u, running = 0u;
#pragma unroll 1
            for (int j = 0; j < VPT; j++) {
                const float e[4] = { v[j].x, v[j].y, v[j].z, v[j].w };
                unsigned eq[4], lc = 0u;
#pragma unroll
                for (int c = 0; c < 4; c++) {
                    eq[c] = (e[c] == thrF) ? 1u : 0u;
                    lc += eq[c];
                }
                unsigned pre = lc;
#pragma unroll
                for (int o = 1; o < 32; o <<= 1) {
                    const unsigned n = __shfl_up_sync(FULL, pre, o);
                    if (lane >= o) pre += n;
                }
                const unsigned excl = pre - lc;
                __syncthreads();
                if (lane == 31) sWsum[warp] = pre;
                __syncthreads();
                unsigned off = 0u, tot = 0u;
#pragma unroll
                for (int w = 0; w < NW; w++) {
                    const unsigned t = sWsum[w];
                    if (w < warp) off += t;
                    tot += t;
                }
                unsigned rr = running + off + excl;
#pragma unroll
                for (int c = 0; c < 4; c++) {
                    if (eq[c]) {
                        if (rr < need) keepMask |= 1u << (4 * j + c);
                        rr++;
                    }
                }
                running += tot;
            }
#pragma unroll
            for (int j = 0; j < VPT; j++) {
                const float e[4] = { v[j].x, v[j].y, v[j].z, v[j].w };
                float o[4];
#pragma unroll
                for (int c = 0; c < 4; c++) {
                    const int i = 4 * j + c;
                    const bool keep = (e[c] > thrF) ||
                                      ((e[c] == thrF) && ((keepMask >> i) & 1u));
                    o[c] = keep ? e[c] : 0.0f;
                }
                float4 ov = { o[0], o[1], o[2], o[3] };
                __stcs(&o4[base + (size_t)j * TPB], ov);
            }
        }

        // fence iteration i's SMEM scalar reads vs iteration i+1's writes
        __syncthreads();                                          // S4
    }
}

extern "C" void kernel_launch(void* const* d_in, const int* in_sizes, int n_in,
                              void* d_out, int out_size) {
    const float4* x4 = (const float4*)d_in[0];
    const int*    kp = (const int*)d_in[1];
    float4*       o4 = (float4*)d_out;
    const int rows = in_sizes[0] / COLS;

    // persistent grid = exact resident capacity (host queries; no allocs)
    int dev = 0, sms = 0, occ = 0;
    cudaGetDevice(&dev);
    cudaDeviceGetAttribute(&sms, cudaDevAttrMultiProcessorCount, dev);
    cudaOccupancyMaxActiveBlocksPerMultiprocessor(&occ, wta_topk_kernel, TPB, 0);
    if (occ < 1) occ = 1;
    int grid = occ * sms;
    if (grid > rows) grid = rows;

    wta_topk_kernel<<<grid, TPB>>>(x4, kp, o4, rows);
}

// round 15
// speedup vs baseline: 1.0111x; 1.0111x over previous
#include <cuda_runtime.h>
#include <cuda_bf16.h>

// WTA / row-wise top-k(=64) scatter-to-dense, exact incl. stable tie-breaking.
// 1 CTA per row (TPB=512), row as raw floats in registers (4x float4).
// Key scheduling idea: ~91% of float4 vectors have all components < 2.0 and
// therefore a known-zero output BEFORE selection -> store them during the
// histogram pass (fills the DRAM-idle select window); defer only vectors
// containing candidates (cmask) to after threshold selection.
// Fast path (valid when count(f>=2.0) >= k; 9-sigma certain for N(0,1) rows):
//   (1) fused 128-bin histogram of (bits>>17)-0x2000 over f >= 2.0 with
//       per-bin slot capture of full bits ([2,6) -> bins 0..95; >=6 clamps
//       to bin 127, resolved exactly by the rank step) + early zero stores
//   (2) warp0: pick bin where reverse-cumulative crosses k (4-chunk suffix
//       scan), then rank the E (expected ~3, dynamically bounded) captured
//       elements with a shuffle loop -> exact k-th value + tie metadata
//   (3) output of deferred vectors only; rare stable tie-break by column.
// Generic fallback (cold, exact): 4-pass 256-bin radix select over fmap keys;
// it re-stores ALL vectors (overwrites early zeros in program order).

#define COLS  8192
#define TPB   512
#define VPT   4                    // float4 per thread -> 16 scalars
#define NW    (TPB / 32)
#define NBIN  128
#define SLOTS 16
#define FULL  0xffffffffu

__device__ __forceinline__ unsigned fmap_u(unsigned b) {
    return b ^ ((unsigned)((int)b >> 31) | 0x80000000u);
}
__device__ __forceinline__ float funmap(unsigned v) {
    unsigned mask = ((unsigned)((int)(~v) >> 31)) | 0x80000000u;
    return __uint_as_float(v ^ mask);
}

__global__ __launch_bounds__(TPB, 4)
void wta_topk_kernel(const float4* __restrict__ x4,
                     const int*    __restrict__ kp,
                     float4*       __restrict__ o4)
{
    __shared__ unsigned sHist[256];          // fast path uses [0,128)
    __shared__ unsigned sBin[NBIN * SLOTS];
    __shared__ unsigned sWsum[NW];
    __shared__ unsigned sSel, sNeed, sEq, sThr, sFlag;

    const int tid  = threadIdx.x;
    const int lane = tid & 31;
    const int warp = tid >> 5;
    const size_t base = (size_t)blockIdx.x * (COLS / 4) + tid;

    // ---- load row (raw floats) ----
    float4 v[VPT];
#pragma unroll
    for (int j = 0; j < VPT; j++)
        v[j] = __ldcs(&x4[base + (size_t)j * TPB]);
    const unsigned k = (unsigned)__ldg(kp);

    if (tid < NBIN) sHist[tid] = 0u;
    if (tid == 0) sFlag = 0u;
    __syncthreads();                                              // S1

    // ---- (1) fused hist + slot capture + EARLY zero stores ----
    const float4 z4 = make_float4(0.0f, 0.0f, 0.0f, 0.0f);
    unsigned cmask = 0u;          // bit j: vector j contains a candidate
#pragma unroll
    for (int j = 0; j < VPT; j++) {
        bool any = false;
#pragma unroll
        for (int c = 0; c < 4; c++) {
            const float f = (c == 0) ? v[j].x : (c == 1) ? v[j].y
                          : (c == 2) ? v[j].z : v[j].w;
            if (f >= 2.0f) {
                any = true;
                const unsigned bits = __float_as_uint(f);
                unsigned b = (bits >> 17) - 0x2000u;   // 2.0 -> bin 0
                b = min(b, 127u);
                const unsigned p = atomicAdd(&sHist[b], 1u);
                if (p < SLOTS) sBin[(b << 4) + p] = bits;
            }
        }
        if (any) cmask |= 1u << j;
        else     __stcs(&o4[base + (size_t)j * TPB], z4);  // output known now
    }
    __syncthreads();                                              // S2

    // ---- (2) warp0: bin select (4 chunks) + dynamic shuffle rank ----
    if (warp == 0) {
        unsigned hv4[4], tot[4];
#pragma unroll
        for (int c = 0; c < 4; c++) {
            hv4[c] = sHist[c * 32 + lane];
            tot[c] = __reduce_add_sync(FULL, hv4[c]);
        }
        unsigned suf = 0u, tch = 0u, exC = 0u;
#pragma unroll
        for (int c = 3; c >= 0; c--) {
            if (suf < k && k <= suf + tot[c]) { tch = (unsigned)c; exC = suf; }
            suf += tot[c];
        }
        if (suf < k) {
            if (lane == 0) sFlag = 1u;
        } else {
            const unsigned hv = hv4[tch];
            unsigned incl = hv;            // suffix sum over higher bins
#pragma unroll
            for (int o = 1; o < 32; o <<= 1) {
                const unsigned n = __shfl_down_sync(FULL, incl, o);
                if (lane + o < 32) incl += n;
            }
            const unsigned excl = incl - hv;
            const bool fired = (exC + excl < k) && (k <= exC + incl);
            const unsigned fm = __ballot_sync(FULL, fired);
            const int src = __ffs(fm) - 1;
            const unsigned selBin = tch * 32u + (unsigned)src;
            const unsigned need1  = k - exC - __shfl_sync(FULL, excl, src);
            const unsigned E      = __shfl_sync(FULL, hv, src);
            if (E > SLOTS) {
                if (lane == 0) sFlag = 1u;
            } else {
                // exact rank among E captured keys (loop bounded by E,
                // warp-uniform, expected ~3); positive-float bits compare
                // identically to values.
                const unsigned key = (lane < (int)E)
                                   ? sBin[(selBin << 4) + lane] : 0u;
                unsigned gt = 0u, eq = 0u;
                for (int o = 0; o < (int)E; o++) {
                    const unsigned other = __shfl_sync(FULL, key, o);
                    gt += (other > key) ? 1u : 0u;
                    eq += (other == key) ? 1u : 0u;
                }
                if (lane < (int)E && gt < need1 && need1 <= gt + eq) {
                    sThr  = key;            // unique key value fires
                    sNeed = need1 - gt;
                    sEq   = eq;
                }
            }
        }
    }
    __syncthreads();                                              // S3

    if (sFlag == 0u) {
        const float thrF = __uint_as_float(sThr);   // thr >= 2.0 here
        const unsigned need = sNeed, eqCnt = sEq;

        if (need == eqCnt) {
            // common path: store only deferred vectors
#pragma unroll
            for (int j = 0; j < VPT; j++) {
                if ((cmask >> j) & 1u) {
                    float4 o;
                    o.x = (v[j].x >= thrF) ? v[j].x : 0.0f;
                    o.y = (v[j].y >= thrF) ? v[j].y : 0.0f;
                    o.z = (v[j].z >= thrF) ? v[j].z : 0.0f;
                    o.w = (v[j].w >= thrF) ? v[j].w : 0.0f;
                    __stcs(&o4[base + (size_t)j * TPB], o);
                }
            }
        } else {
            // rare: stable tie-break, keep first `need` of ==thrF by column
            unsigned keepMask = 0u, running = 0u;
#pragma unroll 1
            for (int j = 0; j < VPT; j++) {
                const float e[4] = { v[j].x, v[j].y, v[j].z, v[j].w };
                unsigned eq[4], lc = 0u;
#pragma unroll
                for (int c = 0; c < 4; c++) {
                    eq[c] = (e[c] == thrF) ? 1u : 0u;
                    lc += eq[c];
                }
                unsigned pre = lc;
#pragma unroll
                for (int o = 1; o < 32; o <<= 1) {
                    const unsigned n = __shfl_up_sync(FULL, pre, o);
                    if (lane >= o) pre += n;
                }
                const unsigned excl = pre - lc;
                __syncthreads();
                if (lane == 31) sWsum[warp] = pre;
                __syncthreads();
                unsigned off = 0u, tot = 0u;
#pragma unroll
                for (int w = 0; w < NW; w++) {
                    const unsigned t = sWsum[w];
                    if (w < warp) off += t;
                    tot += t;
                }
                unsigned r = running + off + excl;
#pragma unroll
                for (int c = 0; c < 4; c++) {
                    if (eq[c]) {
                        if (r < need) keepMask |= 1u << (4 * j + c);
                        r++;
                    }
                }
                running += tot;
            }
#pragma unroll
            for (int j = 0; j < VPT; j++) {
                if ((cmask >> j) & 1u) {     // zero vectors already stored
                    const float e[4] = { v[j].x, v[j].y, v[j].z, v[j].w };
                    float o[4];
#pragma unroll
                    for (int c = 0; c < 4; c++) {
                        const int i = 4 * j + c;
                        const bool keep = (e[c] > thrF) ||
                                          ((e[c] == thrF) && ((keepMask >> i) & 1u));
                        o[c] = keep ? e[c] : 0.0f;
                    }
                    float4 ov = { o[0], o[1], o[2], o[3] };
                    __stcs(&o4[base + (size_t)j * TPB], ov);
                }
            }
        }
    } else {
        // ---- generic fallback: 4-pass 256-bin radix over fmap keys ----
        // thr may be < 2.0 here, so this path re-stores ALL vectors
        // (overwriting the early zeros; same thread, program order).
        unsigned prefix = 0u, need = k;
#pragma unroll 1
        for (int p = 3; p >= 0; p--) {
            const int sh = 8 * p;
            __syncthreads();
            if (tid < 256) sHist[tid] = 0u;
            __syncthreads();
#pragma unroll 1
            for (int j = 0; j < VPT; j++) {
                const float e[4] = { v[j].x, v[j].y, v[j].z, v[j].w };
#pragma unroll
                for (int c = 0; c < 4; c++) {
                    const unsigned key = fmap_u(__float_as_uint(e[c]));
                    const bool m = (p == 3) || (((key ^ prefix) >> (sh + 8)) == 0u);
                    if (m) atomicAdd(&sHist[(key >> sh) & 255u], 1u);
                }
            }
            __syncthreads();
            if (warp == 0) {
                unsigned hv8[8], tot[8];
#pragma unroll
                for (int c = 0; c < 8; c++) {
                    hv8[c] = sHist[c * 32 + lane];
                    tot[c] = __reduce_add_sync(FULL, hv8[c]);
                }
                unsigned suf = 0u, tch = 0u, exC = 0u;
#pragma unroll
                for (int c = 7; c >= 0; c--) {
                    if (suf < need && need <= suf + tot[c]) { tch = (unsigned)c; exC = suf; }
                    suf += tot[c];
                }
                const unsigned hv = hv8[tch];
                unsigned incl = hv;
#pragma unroll
                for (int o = 1; o < 32; o <<= 1) {
                    const unsigned n = __shfl_down_sync(FULL, incl, o);
                    if (lane + o < 32) incl += n;
                }
                const unsigned excl = incl - hv;
                if (exC + excl < need && need <= exC + incl) {
                    sSel  = tch * 32 + (unsigned)lane;
                    sNeed = need - exC - excl;
                    sEq   = hv;
                }
            }
            __syncthreads();
            prefix |= sSel << sh;
            need   = sNeed;
        }
        const unsigned eqCnt = sEq;
        const float thrF = funmap(prefix);

        unsigned keepMask = 0xFFFFFFFFu;
        if (need != eqCnt) {
            keepMask = 0u;
            unsigned running = 0u;
#pragma unroll 1
            for (int j = 0; j < VPT; j++) {
                const float e[4] = { v[j].x, v[j].y, v[j].z, v[j].w };
                unsigned eq[4], lc = 0u;
#pragma unroll
                for (int c = 0; c < 4; c++) {
                    eq[c] = (e[c] == thrF) ? 1u : 0u;
                    lc += eq[c];
                }
                unsigned pre = lc;
#pragma unroll
                for (int o = 1; o < 32; o <<= 1) {
                    const unsigned n = __shfl_up_sync(FULL, pre, o);
                    if (lane >= o) pre += n;
                }
                const unsigned excl = pre - lc;
                __syncthreads();
                if (lane == 31) sWsum[warp] = pre;
                __syncthreads();
                unsigned off = 0u, tot = 0u;
#pragma unroll
                for (int w = 0; w < NW; w++) {
                    const unsigned t = sWsum[w];
                    if (w < warp) off += t;
                    tot += t;
                }
                unsigned r = running + off + excl;
#pragma unroll
                for (int c = 0; c < 4; c++) {
                    if (eq[c]) {
                        if (r < need) keepMask |= 1u << (4 * j + c);
                        r++;
                    }
                }
                running += tot;
            }
        }
#pragma unroll
        for (int j = 0; j < VPT; j++) {
            const float e[4] = { v[j].x, v[j].y, v[j].z, v[j].w };
            float o[4];
#pragma unroll
            for (int c = 0; c < 4; c++) {
                const int i = 4 * j + c;
                const bool keep = (e[c] > thrF) ||
                                  ((e[c] == thrF) && ((keepMask >> i) & 1u));
                o[c] = keep ? e[c] : 0.0f;
            }
            float4 ov = { o[0], o[1], o[2], o[3] };
            __stcs(&o4[base + (size_t)j * TPB], ov);
        }
    }
}

extern "C" void kernel_launch(void* const* d_in, const int* in_sizes, int n_in,
                              void* d_out, int out_size) {
    const float4* x4 = (const float4*)d_in[0];
    const int*    kp = (const int*)d_in[1];
    float4*       o4 = (float4*)d_out;
    const int rows = in_sizes[0] / COLS;
    wta_topk_kernel<<<rows, TPB>>>(x4, kp, o4);
}

// round 16
// speedup vs baseline: 1.0628x; 1.0512x over previous
#include <cuda_runtime.h>
#include <cuda_bf16.h>

// WTA / row-wise top-k(=64) scatter-to-dense, exact incl. stable tie-breaking.
// 1 CTA per row (TPB=512), row as raw floats in registers (4x float4).
// Scheduling: during warp0's selection (the only idle window), warps 1-15
// store their known-zero vectors (no candidate >= 2.0). Each vector is
// stored exactly once; hist loop is untouched (R13 shape).
// Fast path (valid when count(f>=2.0) >= k; 9-sigma certain for N(0,1) rows):
//   (1) fused 128-bin histogram of (bits>>17)-0x2000 over f >= 2.0 with
//       per-bin slot capture of full bits ([2,6) -> bins 0..95; >=6 clamps
//       to bin 127, resolved exactly by the rank step)
//   (2) warp0: pick bin where reverse-cumulative crosses k + shuffle-rank
//       the E (~3) captured elements  ||  warps 1-15: store zero vectors
//   (3) output of remaining vectors; rare stable tie-break by column.
// Generic fallback (cold, exact): 4-pass 256-bin radix select over fmap
// keys; re-stores ALL vectors (overwrites early zeros in program order).

#define COLS  8192
#define TPB   512
#define VPT   4                    // float4 per thread -> 16 scalars
#define NW    (TPB / 32)
#define NBIN  128
#define SLOTS 16
#define FULL  0xffffffffu

__device__ __forceinline__ unsigned fmap_u(unsigned b) {
    return b ^ ((unsigned)((int)b >> 31) | 0x80000000u);
}
__device__ __forceinline__ float funmap(unsigned v) {
    unsigned mask = ((unsigned)((int)(~v) >> 31)) | 0x80000000u;
    return __uint_as_float(v ^ mask);
}

__global__ __launch_bounds__(TPB, 4)
void wta_topk_kernel(const float4* __restrict__ x4,
                     const int*    __restrict__ kp,
                     float4*       __restrict__ o4)
{
    __shared__ unsigned sHist[256];          // fast path uses [0,128)
    __shared__ unsigned sBin[NBIN * SLOTS];
    __shared__ unsigned sWsum[NW];
    __shared__ unsigned sSel, sNeed, sEq, sThr, sFlag;

    const int tid  = threadIdx.x;
    const int lane = tid & 31;
    const int warp = tid >> 5;
    const size_t base = (size_t)blockIdx.x * (COLS / 4) + tid;

    // ---- load row (raw floats) ----
    float4 v[VPT];
#pragma unroll
    for (int j = 0; j < VPT; j++)
        v[j] = __ldcs(&x4[base + (size_t)j * TPB]);
    const unsigned k = (unsigned)__ldg(kp);

    if (tid < NBIN) sHist[tid] = 0u;
    if (tid == 0) sFlag = 0u;
    __syncthreads();                                              // S1

    // ---- (1) fused 128-bin histogram + slot capture over f >= 2.0 ----
    unsigned cmask = 0u;          // bit j: vector j contains a candidate
#pragma unroll
    for (int j = 0; j < VPT; j++) {
        bool any = false;
#pragma unroll
        for (int c = 0; c < 4; c++) {
            const float f = (c == 0) ? v[j].x : (c == 1) ? v[j].y
                          : (c == 2) ? v[j].z : v[j].w;
            if (f >= 2.0f) {
                any = true;
                const unsigned bits = __float_as_uint(f);
                unsigned b = (bits >> 17) - 0x2000u;   // 2.0 -> bin 0
                b = min(b, 127u);
                const unsigned p = atomicAdd(&sHist[b], 1u);
                if (p < SLOTS) sBin[(b << 4) + p] = bits;
            }
        }
        if (any) cmask |= 1u << j;
    }
    __syncthreads();                                              // S2

    // ---- (2) warp0 selects; warps 1-15 store known-zero vectors ----
    if (warp == 0) {
        unsigned hv4[4], tot[4];
#pragma unroll
        for (int c = 0; c < 4; c++) {
            hv4[c] = sHist[c * 32 + lane];
            tot[c] = __reduce_add_sync(FULL, hv4[c]);
        }
        unsigned suf = 0u, tch = 0u, exC = 0u;
#pragma unroll
        for (int c = 3; c >= 0; c--) {
            if (suf < k && k <= suf + tot[c]) { tch = (unsigned)c; exC = suf; }
            suf += tot[c];
        }
        if (suf < k) {
            if (lane == 0) sFlag = 1u;
        } else {
            const unsigned hv = hv4[tch];
            unsigned incl = hv;            // suffix sum over higher bins
#pragma unroll
            for (int o = 1; o < 32; o <<= 1) {
                const unsigned n = __shfl_down_sync(FULL, incl, o);
                if (lane + o < 32) incl += n;
            }
            const unsigned excl = incl - hv;
            const bool fired = (exC + excl < k) && (k <= exC + incl);
            const unsigned fm = __ballot_sync(FULL, fired);
            const int src = __ffs(fm) - 1;
            const unsigned selBin = tch * 32u + (unsigned)src;
            const unsigned need1  = k - exC - __shfl_sync(FULL, excl, src);
            const unsigned E      = __shfl_sync(FULL, hv, src);
            if (E > SLOTS) {
                if (lane == 0) sFlag = 1u;
            } else {
                // exact rank among E captured keys (loop bounded by E,
                // warp-uniform, expected ~3); positive-float bits compare
                // identically to values.
                const unsigned key = (lane < (int)E)
                                   ? sBin[(selBin << 4) + lane] : 0u;
                unsigned gt = 0u, eq = 0u;
                for (int o = 0; o < (int)E; o++) {
                    const unsigned other = __shfl_sync(FULL, key, o);
                    gt += (other > key) ? 1u : 0u;
                    eq += (other == key) ? 1u : 0u;
                }
                if (lane < (int)E && gt < need1 && need1 <= gt + eq) {
                    sThr  = key;            // unique key value fires
                    sNeed = need1 - gt;
                    sEq   = eq;
                }
            }
        }
    } else {
        // idle window: store zero for candidate-free vectors (~91%)
        const float4 z4 = make_float4(0.0f, 0.0f, 0.0f, 0.0f);
#pragma unroll
        for (int j = 0; j < VPT; j++)
            if (!((cmask >> j) & 1u))
                __stcs(&o4[base + (size_t)j * TPB], z4);
    }
    __syncthreads();                                              // S3

    if (sFlag == 0u) {
        const float thrF = __uint_as_float(sThr);   // thr >= 2.0 here
        const unsigned need = sNeed, eqCnt = sEq;
        // warp0 must still store its zero vectors (it was selecting)
        const unsigned smask = (warp == 0) ? 0xFu : cmask;

        if (need == eqCnt) {
            // common path: store remaining vectors
#pragma unroll
            for (int j = 0; j < VPT; j++) {
                if ((smask >> j) & 1u) {
                    float4 o;
                    o.x = (v[j].x >= thrF) ? v[j].x : 0.0f;
                    o.y = (v[j].y >= thrF) ? v[j].y : 0.0f;
                    o.z = (v[j].z >= thrF) ? v[j].z : 0.0f;
                    o.w = (v[j].w >= thrF) ? v[j].w : 0.0f;
                    __stcs(&o4[base + (size_t)j * TPB], o);
                }
            }
        } else {
            // rare: stable tie-break, keep first `need` of ==thrF by column
            unsigned keepMask = 0u, running = 0u;
#pragma unroll 1
            for (int j = 0; j < VPT; j++) {
                const float e[4] = { v[j].x, v[j].y, v[j].z, v[j].w };
                unsigned eq[4], lc = 0u;
#pragma unroll
                for (int c = 0; c < 4; c++) {
                    eq[c] = (e[c] == thrF) ? 1u : 0u;
                    lc += eq[c];
                }
                unsigned pre = lc;
#pragma unroll
                for (int o = 1; o < 32; o <<= 1) {
                    const unsigned n = __shfl_up_sync(FULL, pre, o);
                    if (lane >= o) pre += n;
                }
                const unsigned excl = pre - lc;
                __syncthreads();
                if (lane == 31) sWsum[warp] = pre;
                __syncthreads();
                unsigned off = 0u, tot = 0u;
#pragma unroll
                for (int w = 0; w < NW; w++) {
                    const unsigned t = sWsum[w];
                    if (w < warp) off += t;
                    tot += t;
                }
                unsigned r = running + off + excl;
#pragma unroll
                for (int c = 0; c < 4; c++) {
                    if (eq[c]) {
                        if (r < need) keepMask |= 1u << (4 * j + c);
                        r++;
                    }
                }
                running += tot;
            }
#pragma unroll
            for (int j = 0; j < VPT; j++) {
                if ((smask >> j) & 1u) {
                    const float e[4] = { v[j].x, v[j].y, v[j].z, v[j].w };
                    float o[4];
#pragma unroll
                    for (int c = 0; c < 4; c++) {
                        const int i = 4 * j + c;
                        const bool keep = (e[c] > thrF) ||
                                          ((e[c] == thrF) && ((keepMask >> i) & 1u));
                        o[c] = keep ? e[c] : 0.0f;
                    }
                    float4 ov = { o[0], o[1], o[2], o[3] };
                    __stcs(&o4[base + (size_t)j * TPB], ov);
                }
            }
        }
    } else {
        // ---- generic fallback: 4-pass 256-bin radix over fmap keys ----
        // thr may be < 2.0, so re-store ALL vectors (overwrites early zeros
        // in same-thread program order).
        unsigned prefix = 0u, need = k;
#pragma unroll 1
        for (int p = 3; p >= 0; p--) {
            const int sh = 8 * p;
            __syncthreads();
            if (tid < 256) sHist[tid] = 0u;
            __syncthreads();
#pragma unroll 1
            for (int j = 0; j < VPT; j++) {
                const float e[4] = { v[j].x, v[j].y, v[j].z, v[j].w };
#pragma unroll
                for (int c = 0; c < 4; c++) {
                    const unsigned key = fmap_u(__float_as_uint(e[c]));
                    const bool m = (p == 3) || (((key ^ prefix) >> (sh + 8)) == 0u);
                    if (m) atomicAdd(&sHist[(key >> sh) & 255u], 1u);
                }
            }
            __syncthreads();
            if (warp == 0) {
                unsigned hv8[8], tot[8];
#pragma unroll
                for (int c = 0; c < 8; c++) {
                    hv8[c] = sHist[c * 32 + lane];
                    tot[c] = __reduce_add_sync(FULL, hv8[c]);
                }
                unsigned suf = 0u, tch = 0u, exC = 0u;
#pragma unroll
                for (int c = 7; c >= 0; c--) {
                    if (suf < need && need <= suf + tot[c]) { tch = (unsigned)c; exC = suf; }
                    suf += tot[c];
                }
                const unsigned hv = hv8[tch];
                unsigned incl = hv;
#pragma unroll
                for (int o = 1; o < 32; o <<= 1) {
                    const unsigned n = __shfl_down_sync(FULL, incl, o);
                    if (lane + o < 32) incl += n;
                }
                const unsigned excl = incl - hv;
                if (exC + excl < need && need <= exC + incl) {
                    sSel  = tch * 32 + (unsigned)lane;
                    sNeed = need - exC - excl;
                    sEq   = hv;
                }
            }
            __syncthreads();
            prefix |= sSel << sh;
            need   = sNeed;
        }
        const unsigned eqCnt = sEq;
        const float thrF = funmap(prefix);

        unsigned keepMask = 0xFFFFFFFFu;
        if (need != eqCnt) {
            keepMask = 0u;
            unsigned running = 0u;
#pragma unroll 1
            for (int j = 0; j < VPT; j++) {
                const float e[4] = { v[j].x, v[j].y, v[j].z, v[j].w };
                unsigned eq[4], lc = 0u;
#pragma unroll
                for (int c = 0; c < 4; c++) {
                    eq[c] = (e[c] == thrF) ? 1u : 0u;
                    lc += eq[c];
                }
                unsigned pre = lc;
#pragma unroll
                for (int o = 1; o < 32; o <<= 1) {
                    const unsigned n = __shfl_up_sync(FULL, pre, o);
                    if (lane >= o) pre += n;
                }
                const unsigned excl = pre - lc;
                __syncthreads();
                if (lane == 31) sWsum[warp] = pre;
                __syncthreads();
                unsigned off = 0u, tot = 0u;
#pragma unroll
                for (int w = 0; w < NW; w++) {
                    const unsigned t = sWsum[w];
                    if (w < warp) off += t;
                    tot += t;
                }
                unsigned r = running + off + excl;
#pragma unroll
                for (int c = 0; c < 4; c++) {
                    if (eq[c]) {
                        if (r < need) keepMask |= 1u << (4 * j + c);
                        r++;
                    }
                }
                running += tot;
            }
        }
#pragma unroll
        for (int j = 0; j < VPT; j++) {
            const float e[4] = { v[j].x, v[j].y, v[j].z, v[j].w };
            float o[4];
#pragma unroll
            for (int c = 0; c < 4; c++) {
                const int i = 4 * j + c;
                const bool keep = (e[c] > thrF) ||
                                  ((e[c] == thrF) && ((keepMask >> i) & 1u));
                o[c] = keep ? e[c] : 0.0f;
            }
            float4 ov = { o[0], o[1], o[2], o[3] };
            __stcs(&o4[base + (size_t)j * TPB], ov);
        }
    }
}

extern "C" void kernel_launch(void* const* d_in, const int* in_sizes, int n_in,
                              void* d_out, int out_size) {
    const float4* x4 = (const float4*)d_in[0];
    const int*    kp = (const int*)d_in[1];
    float4*       o4 = (float4*)d_out;
    const int rows = in_sizes[0] / COLS;
    wta_topk_kernel<<<rows, TPB>>>(x4, kp, o4);
}

// round 17
// speedup vs baseline: 1.1912x; 1.1208x over previous
#include <cuda_runtime.h>
#include <cuda_bf16.h>

// WTA / row-wise top-k(=64) scatter-to-dense, exact incl. stable tie-breaking.
// 1 CTA per row (TPB=512), row as raw floats in registers (4x float4).
// R13 body + FIRST-WAVE PHASE STAGGER: co-resident CTAs on an SM start
// wave-aligned (all load, then all compute, then all store -> DRAM idles
// during compute). A one-time nanosleep of slot*T/4 (slot = bid/SMS for the
// first wave only) desynchronizes the 4 SM-slots; replacement CTAs inherit
// the freed slot's phase, so the stagger persists across all waves.
// Fast path (valid when count(f>=2.0) >= k; 9-sigma certain for N(0,1)):
//   (1) fused 128-bin histogram of (bits>>17)-0x2000 over f >= 2.0 with
//       per-bin slot capture of full bits ([2,6) -> bins 0..95; >=6 clamps
//       to bin 127, resolved exactly by the rank step)
//   (2) warp0: pick bin where reverse-cumulative crosses k (4-chunk suffix
//       scan), then rank the E (expected ~3, dynamically bounded) captured
//       elements with a shuffle loop -> exact k-th value + tie metadata
//   (3) output: out = (f >= thr) ? f : 0 ; rare stable tie-break by column.
// Generic fallback (cold, exact): 4-pass 256-bin radix select over fmap keys.

#define COLS  8192
#define TPB   512
#define VPT   4                    // float4 per thread -> 16 scalars
#define NW    (TPB / 32)
#define NBIN  128
#define SLOTS 16
#define SMS   152                  // GB300 SM count (bench target)
#define FULL  0xffffffffu

__device__ __forceinline__ unsigned fmap_u(unsigned b) {
    return b ^ ((unsigned)((int)b >> 31) | 0x80000000u);
}
__device__ __forceinline__ float funmap(unsigned v) {
    unsigned mask = ((unsigned)((int)(~v) >> 31)) | 0x80000000u;
    return __uint_as_float(v ^ mask);
}

__global__ __launch_bounds__(TPB, 4)
void wta_topk_kernel(const float4* __restrict__ x4,
                     const int*    __restrict__ kp,
                     float4*       __restrict__ o4)
{
    __shared__ unsigned sHist[256];          // fast path uses [0,128)
    __shared__ unsigned sBin[NBIN * SLOTS];
    __shared__ unsigned sWsum[NW];
    __shared__ unsigned sSel, sNeed, sEq, sThr, sFlag;

    const int tid  = threadIdx.x;
    const int lane = tid & 31;
    const int warp = tid >> 5;
    const size_t base = (size_t)blockIdx.x * (COLS / 4) + tid;

    // ---- first-wave phase stagger: slot i sleeps i * (CTA_lifetime/4) ----
    // First wave = bids [0, 4*SMS); slot index = bid/SMS under the
    // contiguous-modular CTA->SM map. Later CTAs inherit the freed slot's
    // phase. Deterministic (function of blockIdx only).
    if (blockIdx.x < 4u * SMS) {
        const unsigned slot = blockIdx.x / SMS;     // 0..3
        if (slot) __nanosleep(slot * 1730u);        // ~T/4 steps
    }

    // ---- load row (raw floats) ----
    float4 v[VPT];
#pragma unroll
    for (int j = 0; j < VPT; j++)
        v[j] = __ldcs(&x4[base + (size_t)j * TPB]);
    const unsigned k = (unsigned)__ldg(kp);

    if (tid < NBIN) sHist[tid] = 0u;
    if (tid == 0) sFlag = 0u;
    __syncthreads();                                              // S1

    // ---- (1) fused 128-bin histogram + slot capture over f >= 2.0 ----
#pragma unroll
    for (int j = 0; j < VPT; j++) {
#pragma unroll
        for (int c = 0; c < 4; c++) {
            const float f = (c == 0) ? v[j].x : (c == 1) ? v[j].y
                          : (c == 2) ? v[j].z : v[j].w;
            if (f >= 2.0f) {
                const unsigned bits = __float_as_uint(f);
                unsigned b = (bits >> 17) - 0x2000u;   // 2.0 -> bin 0
                b = min(b, 127u);
                const unsigned p = atomicAdd(&sHist[b], 1u);
                if (p < SLOTS) sBin[(b << 4) + p] = bits;
            }
        }
    }
    __syncthreads();                                              // S2

    // ---- (2) warp0: bin select (4 chunks) + dynamic shuffle rank ----
    if (warp == 0) {
        unsigned hv4[4], tot[4];
#pragma unroll
        for (int c = 0; c < 4; c++) {
            hv4[c] = sHist[c * 32 + lane];
            tot[c] = __reduce_add_sync(FULL, hv4[c]);
        }
        unsigned suf = 0u, tch = 0u, exC = 0u;
#pragma unroll
        for (int c = 3; c >= 0; c--) {
            if (suf < k && k <= suf + tot[c]) { tch = (unsigned)c; exC = suf; }
            suf += tot[c];
        }
        if (suf < k) {
            if (lane == 0) sFlag = 1u;
        } else {
            const unsigned hv = hv4[tch];
            unsigned incl = hv;            // suffix sum over higher bins
#pragma unroll
            for (int o = 1; o < 32; o <<= 1) {
                const unsigned n = __shfl_down_sync(FULL, incl, o);
                if (lane + o < 32) incl += n;
            }
            const unsigned excl = incl - hv;
            const bool fired = (exC + excl < k) && (k <= exC + incl);
            const unsigned fm = __ballot_sync(FULL, fired);
            const int src = __ffs(fm) - 1;
            const unsigned selBin = tch * 32u + (unsigned)src;
            const unsigned need1  = k - exC - __shfl_sync(FULL, excl, src);
            const unsigned E      = __shfl_sync(FULL, hv, src);
            if (E > SLOTS) {
                if (lane == 0) sFlag = 1u;
            } else {
                // exact rank among E captured keys (loop bounded by E,
                // warp-uniform, expected ~3); positive-float bits compare
                // identically to values.
                const unsigned key = (lane < (int)E)
                                   ? sBin[(selBin << 4) + lane] : 0u;
                unsigned gt = 0u, eq = 0u;
                for (int o = 0; o < (int)E; o++) {
                    const unsigned other = __shfl_sync(FULL, key, o);
                    gt += (other > key) ? 1u : 0u;
                    eq += (other == key) ? 1u : 0u;
                }
                if (lane < (int)E && gt < need1 && need1 <= gt + eq) {
                    sThr  = key;            // unique key value fires
                    sNeed = need1 - gt;
                    sEq   = eq;
                }
            }
        }
    }
    __syncthreads();                                              // S3

    float thrF;
    unsigned need, eqCnt;
    if (sFlag == 0u) {
        thrF  = __uint_as_float(sThr);
        need  = sNeed;
        eqCnt = sEq;
    } else {
        // ---- generic fallback: 4-pass 256-bin radix over fmap keys ----
        unsigned prefix = 0u;
        need = k;
#pragma unroll 1
        for (int p = 3; p >= 0; p--) {
            const int sh = 8 * p;
            __syncthreads();
            if (tid < 256) sHist[tid] = 0u;
            __syncthreads();
#pragma unroll 1
            for (int j = 0; j < VPT; j++) {
                const float e[4] = { v[j].x, v[j].y, v[j].z, v[j].w };
#pragma unroll
                for (int c = 0; c < 4; c++) {
                    const unsigned key = fmap_u(__float_as_uint(e[c]));
                    const bool m = (p == 3) || (((key ^ prefix) >> (sh + 8)) == 0u);
                    if (m) atomicAdd(&sHist[(key >> sh) & 255u], 1u);
                }
            }
            __syncthreads();
            if (warp == 0) {
                unsigned hv8[8], tot[8];
#pragma unroll
                for (int c = 0; c < 8; c++) {
                    hv8[c] = sHist[c * 32 + lane];
                    tot[c] = __reduce_add_sync(FULL, hv8[c]);
                }
                unsigned suf = 0u, tch = 0u, exC = 0u;
#pragma unroll
                for (int c = 7; c >= 0; c--) {
                    if (suf < need && need <= suf + tot[c]) { tch = (unsigned)c; exC = suf; }
                    suf += tot[c];
                }
                const unsigned hv = hv8[tch];
                unsigned incl = hv;
#pragma unroll
                for (int o = 1; o < 32; o <<= 1) {
                    const unsigned n = __shfl_down_sync(FULL, incl, o);
                    if (lane + o < 32) incl += n;
                }
                const unsigned excl = incl - hv;
                if (exC + excl < need && need <= exC + incl) {
                    sSel  = tch * 32 + (unsigned)lane;
                    sNeed = need - exC - excl;
                    sEq   = hv;
                }
            }
            __syncthreads();
            prefix |= sSel << sh;
            need   = sNeed;
        }
        eqCnt = sEq;
        thrF  = funmap(prefix);
    }

    // ---- (3) output ----
    if (need == eqCnt) {
        // common path: keep all f >= thrF
#pragma unroll
        for (int j = 0; j < VPT; j++) {
            float4 o;
            o.x = (v[j].x >= thrF) ? v[j].x : 0.0f;
            o.y = (v[j].y >= thrF) ? v[j].y : 0.0f;
            o.z = (v[j].z >= thrF) ? v[j].z : 0.0f;
            o.w = (v[j].w >= thrF) ? v[j].w : 0.0f;
            __stcs(&o4[base + (size_t)j * TPB], o);
        }
    } else {
        // rare: stable tie-break, keep first `need` of ==thrF by column order
        unsigned keepMask = 0u, running = 0u;
#pragma unroll 1
        for (int j = 0; j < VPT; j++) {
            const float e[4] = { v[j].x, v[j].y, v[j].z, v[j].w };
            unsigned eq[4], lc = 0u;
#pragma unroll
            for (int c = 0; c < 4; c++) {
                eq[c] = (e[c] == thrF) ? 1u : 0u;
                lc += eq[c];
            }
            unsigned pre = lc;
#pragma unroll
            for (int o = 1; o < 32; o <<= 1) {
                const unsigned n = __shfl_up_sync(FULL, pre, o);
                if (lane >= o) pre += n;
            }
            const unsigned excl = pre - lc;
            __syncthreads();
            if (lane == 31) sWsum[warp] = pre;
            __syncthreads();
            unsigned off = 0u, tot = 0u;
#pragma unroll
            for (int w = 0; w < NW; w++) {
                const unsigned t = sWsum[w];
                if (w < warp) off += t;
                tot += t;
            }
            unsigned r = running + off + excl;
#pragma unroll
            for (int c = 0; c < 4; c++) {
                if (eq[c]) {
                    if (r < need) keepMask |= 1u << (4 * j + c);
                    r++;
                }
            }
            running += tot;
        }
#pragma unroll
        for (int j = 0; j < VPT; j++) {
            const float e[4] = { v[j].x, v[j].y, v[j].z, v[j].w };
            float o[4];
#pragma unroll
            for (int c = 0; c < 4; c++) {
                const int i = 4 * j + c;
                const bool keep = (e[c] > thrF) ||
                                  ((e[c] == thrF) && ((keepMask >> i) & 1u));
                o[c] = keep ? e[c] : 0.0f;
            }
            float4 ov = { o[0], o[1], o[2], o[3] };
            __stcs(&o4[base + (size_t)j * TPB], ov);
        }
    }
}

extern "C" void kernel_launch(void* const* d_in, const int* in_sizes, int n_in,
                              void* d_out, int out_size) {
    const float4* x4 = (const float4*)d_in[0];
    const int*    kp = (const int*)d_in[1];
    float4*       o4 = (float4*)d_out;
    const int rows = in_sizes[0] / COLS;
    wta_topk_kernel<<<rows, TPB>>>(x4, kp, o4);
}